// round 14
// baseline (speedup 1.0000x reference)
#include <cuda_runtime.h>
#include <math.h>

#define BB 8
#define TT 16384
#define RC 32
#define CLS 256
#define ECH 256
#define NL 40
#define DILATION 1024
#define BT (BB*TT)
#define SLOT_BN1 39

typedef unsigned long long u64t;

__device__ __forceinline__ u64t splat2(float v){
    u64t d; asm("mov.b64 %0, {%1, %1};" : "=l"(d) : "f"(v)); return d;
}
__device__ __forceinline__ void ffma2(u64t &acc, u64t a, u64t b){
    asm("fma.rn.f32x2 %0, %1, %2, %0;" : "+l"(acc) : "l"(a), "l"(b));
}
__device__ __forceinline__ float2 unpack2(u64t d){
    float2 r; asm("mov.b64 {%0, %1}, %2;" : "=f"(r.x), "=f"(r.y) : "l"(d)); return r;
}

// -------- scratch (device globals; no allocation allowed) --------
__device__ float g_hA[BB*RC*TT];
__device__ float g_hB[BB*RC*TT];
__device__ float g_uA[BB*RC*TT];
__device__ float g_uB[BB*RC*TT];
__device__ float g_skip[BB*RC*TT];
__device__ float g_y[BB*ECH*TT];
__device__ float g_stats2[41*64];    // per-layer per-channel sum/sumsq (slot 39 = bn1)
__device__ float g_stats_e[512];     // bn2 stats

// fused gated activation: tanh(x) * sigmoid(y) with ONE division
__device__ __forceinline__ float gate_act(float x, float y){
    float e2x = __expf(fminf(2.f*x, 30.f));
    float ey  = __expf(fminf(y, 30.f));
    return __fdividef((e2x - 1.f) * ey, (e2x + 1.f) * (1.f + ey));
}
__device__ __forceinline__ float fast_mish(float x){
    float e = __expf(fminf(x, 15.f));
    float p = 1.f + e;
    float p2 = p*p;
    float r = __fdividef(p2 - 1.f, p2 + 1.f);
    return (x > 15.f) ? x : x*r;
}

// ================= start conv: hA = W(32x256) @ shift1(x) + b; skip = 0; zero stats =================
__global__ void __launch_bounds__(256) k_start(const float* __restrict__ x,
                                               const float* __restrict__ sw,
                                               const float* __restrict__ sb){
    __shared__ float sX[32*128];
    __shared__ float sW[32*32];
    int tid = threadIdx.x, blk = blockIdx.x;
    int b = blk >> 7;            // grid = 8 * 128
    int t0 = (blk & 127) << 7;
    if (blk == 0){
        for (int i = tid; i < 41*64; i += 256) g_stats2[i] = 0.f;
        for (int i = tid; i < 512;  i += 256) g_stats_e[i] = 0.f;
    }
    int og = tid >> 6, tj = tid & 63;
    u64t acc[4][2];
    #pragma unroll
    for (int p = 0; p < 4; p++){ acc[p][0]=0ull; acc[p][1]=0ull; }

    for (int ch = 0; ch < 8; ch++){
        int base = ch*32;
        #pragma unroll
        for (int i = 0; i < 16; i++){
            int e = tid + i*256;
            int cc = e >> 7, j = e & 127;
            int gt = t0 + j - 1;
            sX[e] = (gt >= 0) ? x[((size_t)(b*CLS + base + cc))*TT + gt] : 0.f;
        }
        #pragma unroll
        for (int i = 0; i < 4; i++){
            int e = tid + i*256;
            int k = e >> 5, o = e & 31;
            sW[e] = sw[o*CLS + base + k];   // sW[k][o]
        }
        __syncthreads();
        #pragma unroll 8
        for (int k = 0; k < 32; k++){
            float2 in = *(const float2*)(sX + k*128 + 2*tj);
            u64t s0 = splat2(in.x), s1 = splat2(in.y);
            const u64t* wp = (const u64t*)(sW + k*32 + 8*og);
            #pragma unroll
            for (int p = 0; p < 4; p++){
                u64t w = wp[p];
                ffma2(acc[p][0], w, s0);
                ffma2(acc[p][1], w, s1);
            }
        }
        __syncthreads();
    }
    int t = t0 + 2*tj;
    #pragma unroll
    for (int p = 0; p < 4; p++){
        float2 v0 = unpack2(acc[p][0]);
        float2 v1 = unpack2(acc[p][1]);
        int c0 = 8*og + 2*p, c1 = c0 + 1;
        float b0 = sb[c0], b1 = sb[c1];
        size_t i0 = ((size_t)(b*RC + c0))*TT + t;
        size_t i1 = ((size_t)(b*RC + c1))*TT + t;
        *(float2*)&g_hA[i0]   = make_float2(v0.x+b0, v1.x+b0);
        *(float2*)&g_hA[i1]   = make_float2(v0.y+b1, v1.y+b1);
        *(float2*)&g_skip[i0] = make_float2(0.f, 0.f);
        *(float2*)&g_skip[i1] = make_float2(0.f, 0.f);
    }
}

// ================= fused layer kernel (R4 config): 256 ts x 64 rows; 2 CTAs/SM =================
__global__ void __launch_bounds__(256, 2) k_layer(
    int L,
    const float* __restrict__ gtw, const float* __restrict__ gtb,
    const float* __restrict__ gsw, const float* __restrict__ gsb,
    const float* __restrict__ rw,  const float* __restrict__ rb,
    const float* __restrict__ gprev, const float* __restrict__ bprev)
{
    extern __shared__ float smem[];
    float* sIn  = smem;              // 64 x 256 = 16384
    float* sW   = smem + 16384;      // 64 x 64 gate weights (transposed, u=2c+s)
    float* sRW  = smem + 20480;      // 32 x 32 residual weights (transposed)
    float* sRed = smem + 21504;      // 64
    float* sAB  = smem + 21568;      // 64

    const bool first = (L == 0);
    const bool last  = (L == NL-1);
    const float* hIn  = (first || (L & 1)) ? g_hA : g_hB;
    float*       hOut = (L & 1) ? g_hB : g_hA;
    const float* uIn  = (L & 1) ? g_uA : g_uB;
    float*       uOut = (L & 1) ? g_uB : g_uA;
    const bool wH = (L >= 1) && !last;

    int tid = threadIdx.x, blk = blockIdx.x;
    int b = blk >> 6;                // grid = 8 * 64
    int t0 = (blk & 63) << 8;
    int og = tid >> 6, tj = tid & 63;
    int lane = tid & 31;

    if (tid < 32){
        float a = 0.f, sh = 0.f;
        if (!first){
            float s = g_stats2[(L-1)*64 + tid];
            float q = g_stats2[(L-1)*64 + 32 + tid];
            float m = s * (1.f/(float)BT);
            float v = q * (1.f/(float)BT) - m*m;
            a  = gprev[tid] * rsqrtf(v + 1e-5f);
            sh = bprev[tid] - m*a;
        }
        sAB[tid] = a; sAB[32+tid] = sh;
    }
    #pragma unroll
    for (int i = 0; i < 16; i++){
        int e = tid + i*256;
        int k = e >> 6, u = e & 63;
        int c = u >> 1, s = u & 1;
        int tap = (k < 32) ? 1 : 0;
        int kk = k & 31;
        const float* wsrc = s ? gsw : gtw;
        sW[e] = wsrc[(c*32 + kk)*2 + tap];
    }
    #pragma unroll
    for (int i = 0; i < 4; i++){
        int e = tid + i*256;
        sRW[e] = rw[(e & 31)*32 + (e >> 5)];
    }
    if (tid < 64) sRed[tid] = 0.f;
    __syncthreads();

    // staging with fused BN-apply of previous layer
    bool dvalid = (t0 >= DILATION);
    #pragma unroll
    for (int i = 0; i < 16; i++){
        int e = tid + i*256;            // float4 idx in 64x256 tile
        int r = e >> 6, j4 = e & 63;
        float4 v = make_float4(0.f,0.f,0.f,0.f);
        if (r < 32 || dvalid){
            int c = (r < 32) ? r : r - 32;
            size_t off = ((size_t)(b*RC + c))*TT + ((r < 32) ? t0 : t0 - DILATION) + 4*j4;
            v = *(const float4*)&hIn[off];
            if (!first){
                float a = sAB[c], sh = sAB[32+c];
                float4 u = *(const float4*)&uIn[off];
                v.x = fmaf(a, u.x, v.x) + sh;
                v.y = fmaf(a, u.y, v.y) + sh;
                v.z = fmaf(a, u.z, v.z) + sh;
                v.w = fmaf(a, u.w, v.w) + sh;
            }
            if (r < 32 && wH) *(float4*)&hOut[off] = v;
        }
        ((float4*)sIn)[e] = v;
    }
    __syncthreads();

    // gate GEMM: 64 k, 8 output-pairs, 4 timesteps (packed f32x2 over output pairs)
    u64t acc[8][4];
    #pragma unroll
    for (int p = 0; p < 8; p++){
        acc[p][0]=0ull; acc[p][1]=0ull; acc[p][2]=0ull; acc[p][3]=0ull;
    }
    const float* wbase = sW + 16*og;
    #pragma unroll 4
    for (int k = 0; k < 64; k++){
        float4 in4 = *(const float4*)(sIn + k*256 + 4*tj);
        u64t s0 = splat2(in4.x), s1 = splat2(in4.y), s2 = splat2(in4.z), s3 = splat2(in4.w);
        const u64t* wp = (const u64t*)(wbase + k*64);
        #pragma unroll
        for (int p = 0; p < 8; p++){
            u64t w = wp[p];
            ffma2(acc[p][0], w, s0);
            ffma2(acc[p][1], w, s1);
            ffma2(acc[p][2], w, s2);
            ffma2(acc[p][3], w, s3);
        }
    }
    __syncthreads();

    // epilogue: gates, skip accumulate, g into smem (or bn1 stats on last layer)
    size_t rowbase = ((size_t)(b*RC))*TT + t0 + 4*tj;
    #pragma unroll
    for (int p = 0; p < 8; p++){
        int c = 8*og + p;
        float tb = gtb[c], sb2 = gsb[c];
        float gv[4];
        #pragma unroll
        for (int ts = 0; ts < 4; ts++){
            float2 a2 = unpack2(acc[p][ts]);   // (tanh-pre, sig-pre)
            gv[ts] = gate_act(a2.x + tb, a2.y + sb2);
        }
        size_t idx = rowbase + (size_t)c*TT;
        float4 sk = *(float4*)&g_skip[idx];
        sk.x += gv[0]; sk.y += gv[1]; sk.z += gv[2]; sk.w += gv[3];
        *(float4*)&g_skip[idx] = sk;
        if (!last){
            sIn[c*256 + 4*tj]     = gv[0];
            sIn[c*256 + 4*tj + 1] = gv[1];
            sIn[c*256 + 4*tj + 2] = gv[2];
            sIn[c*256 + 4*tj + 3] = gv[3];
        } else {
            float s = sk.x+sk.y+sk.z+sk.w;
            float q = sk.x*sk.x+sk.y*sk.y+sk.z*sk.z+sk.w*sk.w;
            #pragma unroll
            for (int off = 16; off > 0; off >>= 1){
                s += __shfl_down_sync(0xffffffffu, s, off);
                q += __shfl_down_sync(0xffffffffu, q, off);
            }
            if (lane == 0){
                atomicAdd(&sRed[c],      s);
                atomicAdd(&sRed[32 + c], q);
            }
        }
    }
    if (last){
        __syncthreads();
        if (tid < 64) atomicAdd(&g_stats2[SLOT_BN1*64 + tid], sRed[tid]);
        return;
    }
    __syncthreads();

    // residual conv: 32 k, 4 output-pairs, 4 timesteps
    u64t racc[4][4];
    #pragma unroll
    for (int p = 0; p < 4; p++){
        racc[p][0]=0ull; racc[p][1]=0ull; racc[p][2]=0ull; racc[p][3]=0ull;
    }
    #pragma unroll 4
    for (int c = 0; c < 32; c++){
        float4 g4 = *(const float4*)(sIn + c*256 + 4*tj);
        u64t s0 = splat2(g4.x), s1 = splat2(g4.y), s2 = splat2(g4.z), s3 = splat2(g4.w);
        const u64t* wp = (const u64t*)(sRW + c*32 + 8*og);
        #pragma unroll
        for (int p = 0; p < 4; p++){
            u64t w = wp[p];
            ffma2(racc[p][0], w, s0);
            ffma2(racc[p][1], w, s1);
            ffma2(racc[p][2], w, s2);
            ffma2(racc[p][3], w, s3);
        }
    }
    #pragma unroll
    for (int p = 0; p < 4; p++){
        float2 v0 = unpack2(racc[p][0]);
        float2 v1 = unpack2(racc[p][1]);
        float2 v2 = unpack2(racc[p][2]);
        float2 v3 = unpack2(racc[p][3]);
        int o0 = 8*og + 2*p, o1 = o0 + 1;
        float bias0 = rb[o0], bias1 = rb[o1];
        float4 u0 = make_float4(v0.x+bias0, v1.x+bias0, v2.x+bias0, v3.x+bias0);
        float4 u1 = make_float4(v0.y+bias1, v1.y+bias1, v2.y+bias1, v3.y+bias1);
        *(float4*)&uOut[rowbase + (size_t)o0*TT] = u0;
        *(float4*)&uOut[rowbase + (size_t)o1*TT] = u1;
        float s0s = u0.x+u0.y+u0.z+u0.w;
        float q0s = u0.x*u0.x+u0.y*u0.y+u0.z*u0.z+u0.w*u0.w;
        float s1s = u1.x+u1.y+u1.z+u1.w;
        float q1s = u1.x*u1.x+u1.y*u1.y+u1.z*u1.z+u1.w*u1.w;
        #pragma unroll
        for (int off = 16; off > 0; off >>= 1){
            s0s += __shfl_down_sync(0xffffffffu, s0s, off);
            q0s += __shfl_down_sync(0xffffffffu, q0s, off);
            s1s += __shfl_down_sync(0xffffffffu, s1s, off);
            q1s += __shfl_down_sync(0xffffffffu, q1s, off);
        }
        if (lane == 0){
            atomicAdd(&sRed[o0],      s0s);
            atomicAdd(&sRed[32 + o0], q0s);
            atomicAdd(&sRed[o1],      s1s);
            atomicAdd(&sRed[32 + o1], q1s);
        }
    }
    __syncthreads();
    if (tid < 64) atomicAdd(&g_stats2[L*64 + tid], sRed[tid]);
}

// ================= e1: y = W1(256x32) @ mish(bn1(skip)) + b1, accumulate bn2 stats =================
__global__ void __launch_bounds__(256) k_e1(const float* __restrict__ w1, const float* __restrict__ b1,
                                            const float* __restrict__ bn1g, const float* __restrict__ bn1b){
    __shared__ float sM[32*64];
    __shared__ float sWT[32*256];
    __shared__ float sRed[512];
    __shared__ float sAB[64];
    int tid = threadIdx.x, blk = blockIdx.x;
    int b = blk >> 8;               // grid = 8 * 256
    int t0 = (blk & 255) << 6;
    if (tid < 32){
        float s = g_stats2[SLOT_BN1*64 + tid];
        float q = g_stats2[SLOT_BN1*64 + 32 + tid];
        float m = s * (1.f/(float)BT);
        float v = q * (1.f/(float)BT) - m*m;
        float a = bn1g[tid] * rsqrtf(v + 1e-5f);
        sAB[tid] = a; sAB[32+tid] = bn1b[tid] - m*a;
    }
    #pragma unroll
    for (int i = 0; i < 32; i++){
        int e = tid + i*256;
        int k = e >> 8, o = e & 255;
        sWT[e] = w1[o*32 + k];
    }
    sRed[tid] = 0.f; sRed[256 + tid] = 0.f;
    __syncthreads();
    #pragma unroll
    for (int i = 0; i < 2; i++){
        int e = tid + i*256;
        int c = e >> 4, j4 = e & 15;
        float4 v = *(const float4*)&g_skip[((size_t)(b*RC + c))*TT + t0 + 4*j4];
        float a = sAB[c], sh = sAB[32+c];
        v.x = fast_mish(fmaf(a, v.x, sh));
        v.y = fast_mish(fmaf(a, v.y, sh));
        v.z = fast_mish(fmaf(a, v.z, sh));
        v.w = fast_mish(fmaf(a, v.w, sh));
        ((float4*)sM)[e] = v;
    }
    __syncthreads();

    int og = tid >> 4, tp = tid & 15;
    u64t acc[8][4];
    #pragma unroll
    for (int p = 0; p < 8; p++){
        acc[p][0]=0ull; acc[p][1]=0ull; acc[p][2]=0ull; acc[p][3]=0ull;
    }
    #pragma unroll 4
    for (int k = 0; k < 32; k++){
        float4 in = *(const float4*)(sM + k*64 + 4*tp);
        u64t s0 = splat2(in.x), s1 = splat2(in.y), s2 = splat2(in.z), s3 = splat2(in.w);
        const u64t* wp = (const u64t*)(sWT + k*256 + 16*og);
        #pragma unroll
        for (int p = 0; p < 8; p++){
            u64t w = wp[p];
            ffma2(acc[p][0], w, s0);
            ffma2(acc[p][1], w, s1);
            ffma2(acc[p][2], w, s2);
            ffma2(acc[p][3], w, s3);
        }
    }
    int lane16 = tid & 15;
    #pragma unroll
    for (int p = 0; p < 8; p++){
        float2 v0 = unpack2(acc[p][0]);
        float2 v1 = unpack2(acc[p][1]);
        float2 v2 = unpack2(acc[p][2]);
        float2 v3 = unpack2(acc[p][3]);
        int o0 = 16*og + 2*p, o1 = o0 + 1;
        float bias0 = b1[o0], bias1 = b1[o1];
        float4 y0 = make_float4(v0.x+bias0, v1.x+bias0, v2.x+bias0, v3.x+bias0);
        float4 y1 = make_float4(v0.y+bias1, v1.y+bias1, v2.y+bias1, v3.y+bias1);
        *(float4*)&g_y[((size_t)(b*ECH + o0))*TT + t0 + 4*tp] = y0;
        *(float4*)&g_y[((size_t)(b*ECH + o1))*TT + t0 + 4*tp] = y1;
        float s0s = y0.x+y0.y+y0.z+y0.w, q0s = y0.x*y0.x+y0.y*y0.y+y0.z*y0.z+y0.w*y0.w;
        float s1s = y1.x+y1.y+y1.z+y1.w, q1s = y1.x*y1.x+y1.y*y1.y+y1.z*y1.z+y1.w*y1.w;
        #pragma unroll
        for (int off = 8; off > 0; off >>= 1){
            s0s += __shfl_xor_sync(0xffffffffu, s0s, off);
            q0s += __shfl_xor_sync(0xffffffffu, q0s, off);
            s1s += __shfl_xor_sync(0xffffffffu, s1s, off);
            q1s += __shfl_xor_sync(0xffffffffu, q1s, off);
        }
        if (lane16 == 0){
            atomicAdd(&sRed[o0],       s0s);
            atomicAdd(&sRed[256 + o0], q0s);
            atomicAdd(&sRed[o1],       s1s);
            atomicAdd(&sRed[256 + o1], q1s);
        }
    }
    __syncthreads();
    atomicAdd(&g_stats_e[tid],       sRed[tid]);
    atomicAdd(&g_stats_e[256 + tid], sRed[256 + tid]);
}

// ================= e2: out = W2(256x256) @ mish(bn2(y)) + b2 =================
__global__ void __launch_bounds__(256, 2) k_e2(const float* __restrict__ w2, const float* __restrict__ b2,
                                               const float* __restrict__ bn2g, const float* __restrict__ bn2b,
                                               float* __restrict__ out){
    extern __shared__ float smem2[];
    float* sM2  = smem2;            // 256 x 64
    float* sWT  = smem2 + 16384;    // 32 x 256 weight chunk
    float* sAB2 = smem2 + 24576;    // 512
    int tid = threadIdx.x, blk = blockIdx.x;
    int b = blk >> 8;
    int t0 = (blk & 255) << 6;
    {
        float s = g_stats_e[tid], q = g_stats_e[256 + tid];
        float m = s * (1.f/(float)BT);
        float v = q * (1.f/(float)BT) - m*m;
        float a = bn2g[tid] * rsqrtf(v + 1e-5f);
        sAB2[tid] = a; sAB2[256 + tid] = bn2b[tid] - m*a;
    }
    __syncthreads();
    #pragma unroll 4
    for (int i = 0; i < 16; i++){
        int e = tid + i*256;
        int c = e >> 4, j4 = e & 15;
        float4 v = *(const float4*)&g_y[((size_t)(b*ECH + c))*TT + t0 + 4*j4];
        float a = sAB2[c], sh = sAB2[256+c];
        v.x = fast_mish(fmaf(a, v.x, sh));
        v.y = fast_mish(fmaf(a, v.y, sh));
        v.z = fast_mish(fmaf(a, v.z, sh));
        v.w = fast_mish(fmaf(a, v.w, sh));
        ((float4*)sM2)[e] = v;
    }
    int og = tid >> 4, tp = tid & 15;
    u64t acc[8][4];
    #pragma unroll
    for (int p = 0; p < 8; p++){
        acc[p][0]=0ull; acc[p][1]=0ull; acc[p][2]=0ull; acc[p][3]=0ull;
    }

    for (int kc = 0; kc < 8; kc++){
        __syncthreads();
        #pragma unroll
        for (int i = 0; i < 32; i++){
            int e = tid + i*256;
            int k = e >> 8, o = e & 255;
            sWT[e] = w2[o*256 + kc*32 + k];
        }
        __syncthreads();
        #pragma unroll 4
        for (int k = 0; k < 32; k++){
            float4 in = *(const float4*)(sM2 + (kc*32 + k)*64 + 4*tp);
            u64t s0 = splat2(in.x), s1 = splat2(in.y), s2 = splat2(in.z), s3 = splat2(in.w);
            const u64t* wp = (const u64t*)(sWT + k*256 + 16*og);
            #pragma unroll
            for (int p = 0; p < 8; p++){
                u64t w = wp[p];
                ffma2(acc[p][0], w, s0);
                ffma2(acc[p][1], w, s1);
                ffma2(acc[p][2], w, s2);
                ffma2(acc[p][3], w, s3);
            }
        }
    }
    #pragma unroll
    for (int p = 0; p < 8; p++){
        float2 v0 = unpack2(acc[p][0]);
        float2 v1 = unpack2(acc[p][1]);
        float2 v2 = unpack2(acc[p][2]);
        float2 v3 = unpack2(acc[p][3]);
        int o0 = 16*og + 2*p, o1 = o0 + 1;
        float bias0 = b2[o0], bias1 = b2[o1];
        *(float4*)&out[((size_t)(b*CLS + o0))*TT + t0 + 4*tp] =
            make_float4(v0.x+bias0, v1.x+bias0, v2.x+bias0, v3.x+bias0);
        *(float4*)&out[((size_t)(b*CLS + o1))*TT + t0 + 4*tp] =
            make_float4(v0.y+bias1, v1.y+bias1, v2.y+bias1, v3.y+bias1);
    }
}

// ================= launch =================
extern "C" void kernel_launch(void* const* d_in, const int* in_sizes, int n_in,
                              void* d_out, int out_size){
    const float* x       = (const float*)d_in[0];
    const float* start_w = (const float*)d_in[1];
    const float* start_b = (const float*)d_in[2];
    const float* gt_w    = (const float*)d_in[3];
    const float* gt_b    = (const float*)d_in[4];
    const float* gs_w    = (const float*)d_in[5];
    const float* gs_b    = (const float*)d_in[6];
    const float* res_w   = (const float*)d_in[7];
    const float* res_b   = (const float*)d_in[8];
    const float* bn_g    = (const float*)d_in[9];
    const float* bn_b    = (const float*)d_in[10];
    const float* bn1_g   = (const float*)d_in[11];
    const float* bn1_b   = (const float*)d_in[12];
    const float* e1_w    = (const float*)d_in[13];
    const float* e1_b    = (const float*)d_in[14];
    const float* bn2_g   = (const float*)d_in[15];
    const float* bn2_b   = (const float*)d_in[16];
    const float* e2_w    = (const float*)d_in[17];
    const float* e2_b    = (const float*)d_in[18];
    float* out = (float*)d_out;

    cudaFuncSetAttribute(k_layer, cudaFuncAttributeMaxDynamicSharedMemorySize, 21632*4);
    cudaFuncSetAttribute(k_e2,    cudaFuncAttributeMaxDynamicSharedMemorySize, 25088*4);

    k_start<<<BB*(TT/128), 256>>>(x, start_w, start_b);

    for (int L = 0; L < NL; L++){
        const float* gp = (L > 0) ? (bn_g + (size_t)(L-1)*RC) : bn_g;
        const float* bp = (L > 0) ? (bn_b + (size_t)(L-1)*RC) : bn_b;
        k_layer<<<BB*(TT/256), 256, 21632*4>>>(
            L,
            gt_w + (size_t)L*RC*RC*2, gt_b + L*RC,
            gs_w + (size_t)L*RC*RC*2, gs_b + L*RC,
            res_w + (size_t)L*RC*RC,  res_b + L*RC,
            gp, bp);
    }

    k_e1<<<BB*(TT/64), 256>>>(e1_w, e1_b, bn1_g, bn1_b);
    k_e2<<<BB*(TT/64), 256, 25088*4>>>(e2_w, e2_b, bn2_g, bn2_b, out);
}

// round 15
// speedup vs baseline: 1.0022x; 1.0022x over previous
#include <cuda_runtime.h>
#include <math.h>

#define BB 8
#define TT 16384
#define RC 32
#define CLS 256
#define ECH 256
#define NL 40
#define DILATION 1024
#define BT (BB*TT)
#define SLOT_BN1 39

typedef unsigned long long u64t;

__device__ __forceinline__ u64t splat2(float v){
    u64t d; asm("mov.b64 %0, {%1, %1};" : "=l"(d) : "f"(v)); return d;
}
__device__ __forceinline__ void ffma2(u64t &acc, u64t a, u64t b){
    asm("fma.rn.f32x2 %0, %1, %2, %0;" : "+l"(acc) : "l"(a), "l"(b));
}
__device__ __forceinline__ float2 unpack2(u64t d){
    float2 r; asm("mov.b64 {%0, %1}, %2;" : "=f"(r.x), "=f"(r.y) : "l"(d)); return r;
}

// -------- scratch (device globals; no allocation allowed) --------
__device__ float g_hA[BB*RC*TT];
__device__ float g_hB[BB*RC*TT];
__device__ float g_uA[BB*RC*TT];
__device__ float g_uB[BB*RC*TT];
__device__ float g_skip[BB*RC*TT];
__device__ float g_y[BB*ECH*TT];
__device__ float g_stats2[41*64];    // per-layer per-channel sum/sumsq (slot 39 = bn1)
__device__ float g_stats_e[512];     // bn2 stats

// fused gated activation: tanh(x) * sigmoid(y) with ONE division
__device__ __forceinline__ float gate_act(float x, float y){
    float e2x = __expf(fminf(2.f*x, 30.f));
    float ey  = __expf(fminf(y, 30.f));
    return __fdividef((e2x - 1.f) * ey, (e2x + 1.f) * (1.f + ey));
}
__device__ __forceinline__ float fast_mish(float x){
    float e = __expf(fminf(x, 15.f));
    float p = 1.f + e;
    float p2 = p*p;
    float r = __fdividef(p2 - 1.f, p2 + 1.f);
    return (x > 15.f) ? x : x*r;
}

// ================= start conv: hA = W(32x256) @ shift1(x) + b; skip = 0; zero stats =================
__global__ void __launch_bounds__(256) k_start(const float* __restrict__ x,
                                               const float* __restrict__ sw,
                                               const float* __restrict__ sb){
    __shared__ float sX[32*128];
    __shared__ float sW[32*32];
    int tid = threadIdx.x, blk = blockIdx.x;
    int b = blk >> 7;            // grid = 8 * 128
    int t0 = (blk & 127) << 7;
    if (blk == 0){
        for (int i = tid; i < 41*64; i += 256) g_stats2[i] = 0.f;
        for (int i = tid; i < 512;  i += 256) g_stats_e[i] = 0.f;
    }
    int og = tid >> 6, tj = tid & 63;
    u64t acc[4][2];
    #pragma unroll
    for (int p = 0; p < 4; p++){ acc[p][0]=0ull; acc[p][1]=0ull; }

    for (int ch = 0; ch < 8; ch++){
        int base = ch*32;
        #pragma unroll
        for (int i = 0; i < 16; i++){
            int e = tid + i*256;
            int cc = e >> 7, j = e & 127;
            int gt = t0 + j - 1;
            sX[e] = (gt >= 0) ? x[((size_t)(b*CLS + base + cc))*TT + gt] : 0.f;
        }
        #pragma unroll
        for (int i = 0; i < 4; i++){
            int e = tid + i*256;
            int k = e >> 5, o = e & 31;
            sW[e] = sw[o*CLS + base + k];   // sW[k][o]
        }
        __syncthreads();
        #pragma unroll 8
        for (int k = 0; k < 32; k++){
            float2 in = *(const float2*)(sX + k*128 + 2*tj);
            u64t s0 = splat2(in.x), s1 = splat2(in.y);
            const u64t* wp = (const u64t*)(sW + k*32 + 8*og);
            #pragma unroll
            for (int p = 0; p < 4; p++){
                u64t w = wp[p];
                ffma2(acc[p][0], w, s0);
                ffma2(acc[p][1], w, s1);
            }
        }
        __syncthreads();
    }
    int t = t0 + 2*tj;
    #pragma unroll
    for (int p = 0; p < 4; p++){
        float2 v0 = unpack2(acc[p][0]);
        float2 v1 = unpack2(acc[p][1]);
        int c0 = 8*og + 2*p, c1 = c0 + 1;
        float b0 = sb[c0], b1 = sb[c1];
        size_t i0 = ((size_t)(b*RC + c0))*TT + t;
        size_t i1 = ((size_t)(b*RC + c1))*TT + t;
        *(float2*)&g_hA[i0]   = make_float2(v0.x+b0, v1.x+b0);
        *(float2*)&g_hA[i1]   = make_float2(v0.y+b1, v1.y+b1);
        *(float2*)&g_skip[i0] = make_float2(0.f, 0.f);
        *(float2*)&g_skip[i1] = make_float2(0.f, 0.f);
    }
}

// ================= fused layer kernel (R4 config): 256 ts x 64 rows; 2 CTAs/SM =================
__global__ void __launch_bounds__(256, 2) k_layer(
    int L,
    const float* __restrict__ gtw, const float* __restrict__ gtb,
    const float* __restrict__ gsw, const float* __restrict__ gsb,
    const float* __restrict__ rw,  const float* __restrict__ rb,
    const float* __restrict__ gprev, const float* __restrict__ bprev)
{
    extern __shared__ float smem[];
    float* sIn  = smem;              // 64 x 256 = 16384
    float* sW   = smem + 16384;      // 64 x 64 gate weights (transposed, u=2c+s)
    float* sRW  = smem + 20480;      // 32 x 32 residual weights (transposed)
    float* sRed = smem + 21504;      // 64
    float* sAB  = smem + 21568;      // 64

    const bool first = (L == 0);
    const bool last  = (L == NL-1);
    const float* hIn  = (first || (L & 1)) ? g_hA : g_hB;
    float*       hOut = (L & 1) ? g_hB : g_hA;
    const float* uIn  = (L & 1) ? g_uA : g_uB;
    float*       uOut = (L & 1) ? g_uB : g_uA;
    const bool wH = (L >= 1) && !last;

    int tid = threadIdx.x, blk = blockIdx.x;
    int b = blk >> 6;                // grid = 8 * 64
    int t0 = (blk & 63) << 8;
    int og = tid >> 6, tj = tid & 63;
    int lane = tid & 31;

    if (tid < 32){
        float a = 0.f, sh = 0.f;
        if (!first){
            float s = g_stats2[(L-1)*64 + tid];
            float q = g_stats2[(L-1)*64 + 32 + tid];
            float m = s * (1.f/(float)BT);
            float v = q * (1.f/(float)BT) - m*m;
            a  = gprev[tid] * rsqrtf(v + 1e-5f);
            sh = bprev[tid] - m*a;
        }
        sAB[tid] = a; sAB[32+tid] = sh;
    }
    #pragma unroll
    for (int i = 0; i < 16; i++){
        int e = tid + i*256;
        int k = e >> 6, u = e & 63;
        int c = u >> 1, s = u & 1;
        int tap = (k < 32) ? 1 : 0;
        int kk = k & 31;
        const float* wsrc = s ? gsw : gtw;
        sW[e] = wsrc[(c*32 + kk)*2 + tap];
    }
    #pragma unroll
    for (int i = 0; i < 4; i++){
        int e = tid + i*256;
        sRW[e] = rw[(e & 31)*32 + (e >> 5)];
    }
    if (tid < 64) sRed[tid] = 0.f;
    __syncthreads();

    // staging with fused BN-apply of previous layer
    bool dvalid = (t0 >= DILATION);
    #pragma unroll
    for (int i = 0; i < 16; i++){
        int e = tid + i*256;            // float4 idx in 64x256 tile
        int r = e >> 6, j4 = e & 63;
        float4 v = make_float4(0.f,0.f,0.f,0.f);
        if (r < 32 || dvalid){
            int c = (r < 32) ? r : r - 32;
            size_t off = ((size_t)(b*RC + c))*TT + ((r < 32) ? t0 : t0 - DILATION) + 4*j4;
            v = *(const float4*)&hIn[off];
            if (!first){
                float a = sAB[c], sh = sAB[32+c];
                float4 u = *(const float4*)&uIn[off];
                v.x = fmaf(a, u.x, v.x) + sh;
                v.y = fmaf(a, u.y, v.y) + sh;
                v.z = fmaf(a, u.z, v.z) + sh;
                v.w = fmaf(a, u.w, v.w) + sh;
            }
            if (r < 32 && wH) *(float4*)&hOut[off] = v;
        }
        ((float4*)sIn)[e] = v;
    }
    __syncthreads();

    // gate GEMM: 64 k, 8 output-pairs, 4 timesteps (packed f32x2 over output pairs)
    u64t acc[8][4];
    #pragma unroll
    for (int p = 0; p < 8; p++){
        acc[p][0]=0ull; acc[p][1]=0ull; acc[p][2]=0ull; acc[p][3]=0ull;
    }
    const float* wbase = sW + 16*og;
    #pragma unroll 4
    for (int k = 0; k < 64; k++){
        float4 in4 = *(const float4*)(sIn + k*256 + 4*tj);
        u64t s0 = splat2(in4.x), s1 = splat2(in4.y), s2 = splat2(in4.z), s3 = splat2(in4.w);
        const u64t* wp = (const u64t*)(wbase + k*64);
        #pragma unroll
        for (int p = 0; p < 8; p++){
            u64t w = wp[p];
            ffma2(acc[p][0], w, s0);
            ffma2(acc[p][1], w, s1);
            ffma2(acc[p][2], w, s2);
            ffma2(acc[p][3], w, s3);
        }
    }
    __syncthreads();

    // epilogue: gates, skip accumulate, g into smem (or bn1 stats on last layer)
    size_t rowbase = ((size_t)(b*RC))*TT + t0 + 4*tj;
    #pragma unroll
    for (int p = 0; p < 8; p++){
        int c = 8*og + p;
        float tb = gtb[c], sb2 = gsb[c];
        float gv[4];
        #pragma unroll
        for (int ts = 0; ts < 4; ts++){
            float2 a2 = unpack2(acc[p][ts]);   // (tanh-pre, sig-pre)
            gv[ts] = gate_act(a2.x + tb, a2.y + sb2);
        }
        size_t idx = rowbase + (size_t)c*TT;
        float4 sk = *(float4*)&g_skip[idx];
        sk.x += gv[0]; sk.y += gv[1]; sk.z += gv[2]; sk.w += gv[3];
        *(float4*)&g_skip[idx] = sk;
        if (!last){
            sIn[c*256 + 4*tj]     = gv[0];
            sIn[c*256 + 4*tj + 1] = gv[1];
            sIn[c*256 + 4*tj + 2] = gv[2];
            sIn[c*256 + 4*tj + 3] = gv[3];
        } else {
            float s = sk.x+sk.y+sk.z+sk.w;
            float q = sk.x*sk.x+sk.y*sk.y+sk.z*sk.z+sk.w*sk.w;
            #pragma unroll
            for (int off = 16; off > 0; off >>= 1){
                s += __shfl_down_sync(0xffffffffu, s, off);
                q += __shfl_down_sync(0xffffffffu, q, off);
            }
            if (lane == 0){
                atomicAdd(&sRed[c],      s);
                atomicAdd(&sRed[32 + c], q);
            }
        }
    }
    if (last){
        __syncthreads();
        if (tid < 64) atomicAdd(&g_stats2[SLOT_BN1*64 + tid], sRed[tid]);
        return;
    }
    __syncthreads();

    // residual conv: 32 k, 4 output-pairs, 4 timesteps
    u64t racc[4][4];
    #pragma unroll
    for (int p = 0; p < 4; p++){
        racc[p][0]=0ull; racc[p][1]=0ull; racc[p][2]=0ull; racc[p][3]=0ull;
    }
    #pragma unroll 4
    for (int c = 0; c < 32; c++){
        float4 g4 = *(const float4*)(sIn + c*256 + 4*tj);
        u64t s0 = splat2(g4.x), s1 = splat2(g4.y), s2 = splat2(g4.z), s3 = splat2(g4.w);
        const u64t* wp = (const u64t*)(sRW + c*32 + 8*og);
        #pragma unroll
        for (int p = 0; p < 4; p++){
            u64t w = wp[p];
            ffma2(racc[p][0], w, s0);
            ffma2(racc[p][1], w, s1);
            ffma2(racc[p][2], w, s2);
            ffma2(racc[p][3], w, s3);
        }
    }
    #pragma unroll
    for (int p = 0; p < 4; p++){
        float2 v0 = unpack2(racc[p][0]);
        float2 v1 = unpack2(racc[p][1]);
        float2 v2 = unpack2(racc[p][2]);
        float2 v3 = unpack2(racc[p][3]);
        int o0 = 8*og + 2*p, o1 = o0 + 1;
        float bias0 = rb[o0], bias1 = rb[o1];
        float4 u0 = make_float4(v0.x+bias0, v1.x+bias0, v2.x+bias0, v3.x+bias0);
        float4 u1 = make_float4(v0.y+bias1, v1.y+bias1, v2.y+bias1, v3.y+bias1);
        *(float4*)&uOut[rowbase + (size_t)o0*TT] = u0;
        *(float4*)&uOut[rowbase + (size_t)o1*TT] = u1;
        float s0s = u0.x+u0.y+u0.z+u0.w;
        float q0s = u0.x*u0.x+u0.y*u0.y+u0.z*u0.z+u0.w*u0.w;
        float s1s = u1.x+u1.y+u1.z+u1.w;
        float q1s = u1.x*u1.x+u1.y*u1.y+u1.z*u1.z+u1.w*u1.w;
        #pragma unroll
        for (int off = 16; off > 0; off >>= 1){
            s0s += __shfl_down_sync(0xffffffffu, s0s, off);
            q0s += __shfl_down_sync(0xffffffffu, q0s, off);
            s1s += __shfl_down_sync(0xffffffffu, s1s, off);
            q1s += __shfl_down_sync(0xffffffffu, q1s, off);
        }
        if (lane == 0){
            atomicAdd(&sRed[o0],      s0s);
            atomicAdd(&sRed[32 + o0], q0s);
            atomicAdd(&sRed[o1],      s1s);
            atomicAdd(&sRed[32 + o1], q1s);
        }
    }
    __syncthreads();
    if (tid < 64) atomicAdd(&g_stats2[L*64 + tid], sRed[tid]);
}

// ================= e1: y = W1(256x32) @ mish(bn1(skip)) + b1, accumulate bn2 stats =================
__global__ void __launch_bounds__(256) k_e1(const float* __restrict__ w1, const float* __restrict__ b1,
                                            const float* __restrict__ bn1g, const float* __restrict__ bn1b){
    __shared__ float sM[32*64];
    __shared__ float sWT[32*256];
    __shared__ float sRed[512];
    __shared__ float sAB[64];
    int tid = threadIdx.x, blk = blockIdx.x;
    int b = blk >> 8;               // grid = 8 * 256
    int t0 = (blk & 255) << 6;
    if (tid < 32){
        float s = g_stats2[SLOT_BN1*64 + tid];
        float q = g_stats2[SLOT_BN1*64 + 32 + tid];
        float m = s * (1.f/(float)BT);
        float v = q * (1.f/(float)BT) - m*m;
        float a = bn1g[tid] * rsqrtf(v + 1e-5f);
        sAB[tid] = a; sAB[32+tid] = bn1b[tid] - m*a;
    }
    #pragma unroll
    for (int i = 0; i < 32; i++){
        int e = tid + i*256;
        int k = e >> 8, o = e & 255;
        sWT[e] = w1[o*32 + k];
    }
    sRed[tid] = 0.f; sRed[256 + tid] = 0.f;
    __syncthreads();
    #pragma unroll
    for (int i = 0; i < 2; i++){
        int e = tid + i*256;
        int c = e >> 4, j4 = e & 15;
        float4 v = *(const float4*)&g_skip[((size_t)(b*RC + c))*TT + t0 + 4*j4];
        float a = sAB[c], sh = sAB[32+c];
        v.x = fast_mish(fmaf(a, v.x, sh));
        v.y = fast_mish(fmaf(a, v.y, sh));
        v.z = fast_mish(fmaf(a, v.z, sh));
        v.w = fast_mish(fmaf(a, v.w, sh));
        ((float4*)sM)[e] = v;
    }
    __syncthreads();

    int og = tid >> 4, tp = tid & 15;
    u64t acc[8][4];
    #pragma unroll
    for (int p = 0; p < 8; p++){
        acc[p][0]=0ull; acc[p][1]=0ull; acc[p][2]=0ull; acc[p][3]=0ull;
    }
    #pragma unroll 4
    for (int k = 0; k < 32; k++){
        float4 in = *(const float4*)(sM + k*64 + 4*tp);
        u64t s0 = splat2(in.x), s1 = splat2(in.y), s2 = splat2(in.z), s3 = splat2(in.w);
        const u64t* wp = (const u64t*)(sWT + k*256 + 16*og);
        #pragma unroll
        for (int p = 0; p < 8; p++){
            u64t w = wp[p];
            ffma2(acc[p][0], w, s0);
            ffma2(acc[p][1], w, s1);
            ffma2(acc[p][2], w, s2);
            ffma2(acc[p][3], w, s3);
        }
    }
    int lane16 = tid & 15;
    #pragma unroll
    for (int p = 0; p < 8; p++){
        float2 v0 = unpack2(acc[p][0]);
        float2 v1 = unpack2(acc[p][1]);
        float2 v2 = unpack2(acc[p][2]);
        float2 v3 = unpack2(acc[p][3]);
        int o0 = 16*og + 2*p, o1 = o0 + 1;
        float bias0 = b1[o0], bias1 = b1[o1];
        float4 y0 = make_float4(v0.x+bias0, v1.x+bias0, v2.x+bias0, v3.x+bias0);
        float4 y1 = make_float4(v0.y+bias1, v1.y+bias1, v2.y+bias1, v3.y+bias1);
        *(float4*)&g_y[((size_t)(b*ECH + o0))*TT + t0 + 4*tp] = y0;
        *(float4*)&g_y[((size_t)(b*ECH + o1))*TT + t0 + 4*tp] = y1;
        float s0s = y0.x+y0.y+y0.z+y0.w, q0s = y0.x*y0.x+y0.y*y0.y+y0.z*y0.z+y0.w*y0.w;
        float s1s = y1.x+y1.y+y1.z+y1.w, q1s = y1.x*y1.x+y1.y*y1.y+y1.z*y1.z+y1.w*y1.w;
        #pragma unroll
        for (int off = 8; off > 0; off >>= 1){
            s0s += __shfl_xor_sync(0xffffffffu, s0s, off);
            q0s += __shfl_xor_sync(0xffffffffu, q0s, off);
            s1s += __shfl_xor_sync(0xffffffffu, s1s, off);
            q1s += __shfl_xor_sync(0xffffffffu, q1s, off);
        }
        if (lane16 == 0){
            atomicAdd(&sRed[o0],       s0s);
            atomicAdd(&sRed[256 + o0], q0s);
            atomicAdd(&sRed[o1],       s1s);
            atomicAdd(&sRed[256 + o1], q1s);
        }
    }
    __syncthreads();
    atomicAdd(&g_stats_e[tid],       sRed[tid]);
    atomicAdd(&g_stats_e[256 + tid], sRed[256 + tid]);
}

// ================= e2: out = W2(256x256) @ mish(bn2(y)) + b2 =================
__global__ void __launch_bounds__(256, 2) k_e2(const float* __restrict__ w2, const float* __restrict__ b2,
                                               const float* __restrict__ bn2g, const float* __restrict__ bn2b,
                                               float* __restrict__ out){
    extern __shared__ float smem2[];
    float* sM2  = smem2;            // 256 x 64
    float* sWT  = smem2 + 16384;    // 32 x 256 weight chunk
    float* sAB2 = smem2 + 24576;    // 512
    int tid = threadIdx.x, blk = blockIdx.x;
    int b = blk >> 8;
    int t0 = (blk & 255) << 6;
    {
        float s = g_stats_e[tid], q = g_stats_e[256 + tid];
        float m = s * (1.f/(float)BT);
        float v = q * (1.f/(float)BT) - m*m;
        float a = bn2g[tid] * rsqrtf(v + 1e-5f);
        sAB2[tid] = a; sAB2[256 + tid] = bn2b[tid] - m*a;
    }
    __syncthreads();
    #pragma unroll 4
    for (int i = 0; i < 16; i++){
        int e = tid + i*256;
        int c = e >> 4, j4 = e & 15;
        float4 v = *(const float4*)&g_y[((size_t)(b*ECH + c))*TT + t0 + 4*j4];
        float a = sAB2[c], sh = sAB2[256+c];
        v.x = fast_mish(fmaf(a, v.x, sh));
        v.y = fast_mish(fmaf(a, v.y, sh));
        v.z = fast_mish(fmaf(a, v.z, sh));
        v.w = fast_mish(fmaf(a, v.w, sh));
        ((float4*)sM2)[e] = v;
    }
    int og = tid >> 4, tp = tid & 15;
    u64t acc[8][4];
    #pragma unroll
    for (int p = 0; p < 8; p++){
        acc[p][0]=0ull; acc[p][1]=0ull; acc[p][2]=0ull; acc[p][3]=0ull;
    }

    for (int kc = 0; kc < 8; kc++){
        __syncthreads();
        #pragma unroll
        for (int i = 0; i < 32; i++){
            int e = tid + i*256;
            int k = e >> 8, o = e & 255;
            sWT[e] = w2[o*256 + kc*32 + k];
        }
        __syncthreads();
        #pragma unroll 4
        for (int k = 0; k < 32; k++){
            float4 in = *(const float4*)(sM2 + (kc*32 + k)*64 + 4*tp);
            u64t s0 = splat2(in.x), s1 = splat2(in.y), s2 = splat2(in.z), s3 = splat2(in.w);
            const u64t* wp = (const u64t*)(sWT + k*256 + 16*og);
            #pragma unroll
            for (int p = 0; p < 8; p++){
                u64t w = wp[p];
                ffma2(acc[p][0], w, s0);
                ffma2(acc[p][1], w, s1);
                ffma2(acc[p][2], w, s2);
                ffma2(acc[p][3], w, s3);
            }
        }
    }
    #pragma unroll
    for (int p = 0; p < 8; p++){
        float2 v0 = unpack2(acc[p][0]);
        float2 v1 = unpack2(acc[p][1]);
        float2 v2 = unpack2(acc[p][2]);
        float2 v3 = unpack2(acc[p][3]);
        int o0 = 16*og + 2*p, o1 = o0 + 1;
        float bias0 = b2[o0], bias1 = b2[o1];
        *(float4*)&out[((size_t)(b*CLS + o0))*TT + t0 + 4*tp] =
            make_float4(v0.x+bias0, v1.x+bias0, v2.x+bias0, v3.x+bias0);
        *(float4*)&out[((size_t)(b*CLS + o1))*TT + t0 + 4*tp] =
            make_float4(v0.y+bias1, v1.y+bias1, v2.y+bias1, v3.y+bias1);
    }
}

// ================= launch =================
extern "C" void kernel_launch(void* const* d_in, const int* in_sizes, int n_in,
                              void* d_out, int out_size){
    const float* x       = (const float*)d_in[0];
    const float* start_w = (const float*)d_in[1];
    const float* start_b = (const float*)d_in[2];
    const float* gt_w    = (const float*)d_in[3];
    const float* gt_b    = (const float*)d_in[4];
    const float* gs_w    = (const float*)d_in[5];
    const float* gs_b    = (const float*)d_in[6];
    const float* res_w   = (const float*)d_in[7];
    const float* res_b   = (const float*)d_in[8];
    const float* bn_g    = (const float*)d_in[9];
    const float* bn_b    = (const float*)d_in[10];
    const float* bn1_g   = (const float*)d_in[11];
    const float* bn1_b   = (const float*)d_in[12];
    const float* e1_w    = (const float*)d_in[13];
    const float* e1_b    = (const float*)d_in[14];
    const float* bn2_g   = (const float*)d_in[15];
    const float* bn2_b   = (const float*)d_in[16];
    const float* e2_w    = (const float*)d_in[17];
    const float* e2_b    = (const float*)d_in[18];
    float* out = (float*)d_out;

    cudaFuncSetAttribute(k_layer, cudaFuncAttributeMaxDynamicSharedMemorySize, 21632*4);
    cudaFuncSetAttribute(k_e2,    cudaFuncAttributeMaxDynamicSharedMemorySize, 25088*4);

    k_start<<<BB*(TT/128), 256>>>(x, start_w, start_b);

    for (int L = 0; L < NL; L++){
        const float* gp = (L > 0) ? (bn_g + (size_t)(L-1)*RC) : bn_g;
        const float* bp = (L > 0) ? (bn_b + (size_t)(L-1)*RC) : bn_b;
        k_layer<<<BB*(TT/256), 256, 21632*4>>>(
            L,
            gt_w + (size_t)L*RC*RC*2, gt_b + L*RC,
            gs_w + (size_t)L*RC*RC*2, gs_b + L*RC,
            res_w + (size_t)L*RC*RC,  res_b + L*RC,
            gp, bp);
    }

    k_e1<<<BB*(TT/64), 256>>>(e1_w, e1_b, bn1_g, bn1_b);
    k_e2<<<BB*(TT/64), 256, 25088*4>>>(e2_w, e2_b, bn2_g, bn2_b, out);
}